// round 4
// baseline (speedup 1.0000x reference)
#include <cuda_runtime.h>
#include <cuda_bf16.h>
#include <cstdint>
#include <math.h>

// ---------------------------------------------------------------------------
// Problem dims
// ---------------------------------------------------------------------------
#define B_DIM 32
#define T_DIM 512
#define K_DIM 1024
#define N_DIM 1024
#define M_DIM (B_DIM * T_DIM)   // 16384

#define DELTA 1e-3f             // flag margin (~22 sigma of observed GEMM error)

// ---------------------------------------------------------------------------
// Static device scratch (allocation-guard safe)
// ---------------------------------------------------------------------------
__device__ float g_Y[(size_t)M_DIM * N_DIM];                 // 64 MB pre-activations
__device__ __nv_bfloat16 gA1[(size_t)M_DIM * K_DIM];
__device__ __nv_bfloat16 gA2[(size_t)M_DIM * K_DIM];
__device__ __nv_bfloat16 gA3[(size_t)M_DIM * K_DIM];
__device__ __nv_bfloat16 gW1[(size_t)N_DIM * K_DIM];
__device__ __nv_bfloat16 gW2[(size_t)N_DIM * K_DIM];
__device__ __nv_bfloat16 gW3[(size_t)N_DIM * K_DIM];
__device__ int g_count;
__device__ int g_list[B_DIM * N_DIM];                        // flagged chain ids

// ---------------------------------------------------------------------------
// PTX helpers (sm_100-generic: cp.async, ldmatrix, mma.sync)
// ---------------------------------------------------------------------------
__device__ __forceinline__ uint32_t smem_u32(const void* p) {
    uint32_t a;
    asm("{ .reg .u64 t; cvta.to.shared.u64 t, %1; cvt.u32.u64 %0, t; }" : "=r"(a) : "l"(p));
    return a;
}

__device__ __forceinline__ void cp_async16(uint32_t sm, const void* g) {
    asm volatile("cp.async.cg.shared.global [%0], [%1], 16;" :: "r"(sm), "l"(g));
}
#define CP_ASYNC_COMMIT() asm volatile("cp.async.commit_group;" ::: "memory")
#define CP_ASYNC_WAIT_1() asm volatile("cp.async.wait_group 1;" ::: "memory")

#define LDSM4(r, addr) \
    asm volatile("ldmatrix.sync.aligned.m8n8.x4.shared.b16 {%0,%1,%2,%3}, [%4];" \
        : "=r"((r)[0]), "=r"((r)[1]), "=r"((r)[2]), "=r"((r)[3]) : "r"(addr))

#define MMA16816(acc, a, b0, b1) \
    asm volatile("mma.sync.aligned.m16n8k16.row.col.f32.bf16.bf16.f32 " \
        "{%0,%1,%2,%3}, {%4,%5,%6,%7}, {%8,%9}, {%0,%1,%2,%3};" \
        : "+f"((acc)[0]), "+f"((acc)[1]), "+f"((acc)[2]), "+f"((acc)[3]) \
        : "r"((a)[0]), "r"((a)[1]), "r"((a)[2]), "r"((a)[3]), "r"(b0), "r"(b1))

// ---------------------------------------------------------------------------
// Split: fp32 -> 3-way bf16 decomposition (24 mantissa bits). Also zeroes
// the flagged-chain counter for this graph replay.
// ---------------------------------------------------------------------------
__device__ __forceinline__ void split3(float x, __nv_bfloat16& a, __nv_bfloat16& b, __nv_bfloat16& c) {
    a = __float2bfloat16(x);
    float r = x - __bfloat162float(a);
    b = __float2bfloat16(r);
    float r2 = r - __bfloat162float(b);
    c = __float2bfloat16(r2);
}

__global__ void __launch_bounds__(256)
split_kernel(const float* __restrict__ X, const float* __restrict__ W)
{
    if (blockIdx.x == 0 && threadIdx.x == 0) g_count = 0;

    const size_t NX = (size_t)M_DIM * K_DIM;
    size_t i = ((size_t)blockIdx.x * blockDim.x + threadIdx.x) * 2;
    float2 x;
    __nv_bfloat16 *p1, *p2, *p3;
    if (i < NX) {
        x = *(const float2*)(X + i);
        p1 = gA1 + i; p2 = gA2 + i; p3 = gA3 + i;
    } else {
        size_t j = i - NX;
        x = *(const float2*)(W + j);
        p1 = gW1 + j; p2 = gW2 + j; p3 = gW3 + j;
    }
    __nv_bfloat16 a0, b0, c0, a1, b1, c1;
    split3(x.x, a0, b0, c0);
    split3(x.y, a1, b1, c1);
    __nv_bfloat162 v1; v1.x = a0; v1.y = a1;
    __nv_bfloat162 v2; v2.x = b0; v2.y = b1;
    __nv_bfloat162 v3; v3.x = c0; v3.y = c1;
    *(__nv_bfloat162*)p1 = v1;
    *(__nv_bfloat162*)p2 = v2;
    *(__nv_bfloat162*)p3 = v3;
}

// ---------------------------------------------------------------------------
// HMMA GEMM: Y = sum over 6 segments of Ai @ Wj^T (fp32 accum in registers)
// BM=128, BN=128, BK=32, 3-stage cp.async pipeline, 8 warps (4m x 2n).
// ---------------------------------------------------------------------------
#define BK 32
#define PAD_ROW 40
#define STAGE_ELEMS (128 * PAD_ROW)
#define STAGE_BYTES (STAGE_ELEMS * 2)          // 10240
#define NSTAGE 3
#define B_SMEM_OFF (NSTAGE * STAGE_BYTES)
#define SMEM_TOTAL (2 * NSTAGE * STAGE_BYTES)  // 61440
#define NUM_CHUNKS 192

__global__ void __launch_bounds__(256, 2)
gemm_kernel()
{
    extern __shared__ __align__(16) char smem[];
    const uint32_t sbase = smem_u32(smem);
    const int tid = threadIdx.x;
    const int lane = tid & 31;
    const int w = tid >> 5;
    const int wm = w >> 1;
    const int wn = w & 1;

    const int bm = blockIdx.y * 128;
    const int bn = blockIdx.x * 128;

    const int a_row = wm * 32 + (lane & 15);
    const int a_colb = (lane >> 4) << 3;
    const int b_n = (lane & 7) + ((lane >> 4) << 3);
    const int b_k = ((lane >> 3) & 1) << 3;

    float acc[2][8][4];
#pragma unroll
    for (int i = 0; i < 2; i++)
#pragma unroll
        for (int j = 0; j < 8; j++)
#pragma unroll
            for (int q = 0; q < 4; q++) acc[i][j][q] = 0.0f;

    auto seg_ptrs = [&](int seg, const __nv_bfloat16*& Ap, const __nv_bfloat16*& Wp) {
        switch (seg) {
            case 0: Ap = gA1; Wp = gW1; break;
            case 1: Ap = gA1; Wp = gW2; break;
            case 2: Ap = gA2; Wp = gW1; break;
            case 3: Ap = gA1; Wp = gW3; break;
            case 4: Ap = gA2; Wp = gW2; break;
            default: Ap = gA3; Wp = gW1; break;
        }
    };

    auto load_chunk = [&](int c, int s) {
        const __nv_bfloat16 *Ap, *Wp;
        seg_ptrs(c >> 5, Ap, Wp);
        const int kb = c & 31;
        const char* Ag = (const char*)(Ap + (size_t)bm * K_DIM + kb * BK);
        const char* Wg = (const char*)(Wp + (size_t)bn * K_DIM + kb * BK);
        const uint32_t sA = sbase + s * STAGE_BYTES;
        const uint32_t sB = sbase + B_SMEM_OFF + s * STAGE_BYTES;
#pragma unroll
        for (int i = 0; i < 2; i++) {
            int v = i * 256 + tid;
            int row = v >> 2, ch = (v & 3) * 16;
            cp_async16(sA + row * 80 + ch, Ag + (size_t)row * (K_DIM * 2) + ch);
            cp_async16(sB + row * 80 + ch, Wg + (size_t)row * (K_DIM * 2) + ch);
        }
    };

    auto compute_stage = [&](int s) {
        const uint32_t aA = sbase + s * STAGE_BYTES;
        const uint32_t aB = sbase + B_SMEM_OFF + s * STAGE_BYTES;
#pragma unroll
        for (int ks = 0; ks < 2; ks++) {
            uint32_t a0[4], a1[4];
            LDSM4(a0, aA + (uint32_t)(a_row) * 80 + (a_colb + ks * 16) * 2);
            LDSM4(a1, aA + (uint32_t)(a_row + 16) * 80 + (a_colb + ks * 16) * 2);
#pragma unroll
            for (int jp = 0; jp < 4; jp++) {
                uint32_t b[4];
                LDSM4(b, aB + (uint32_t)(wn * 64 + jp * 16 + b_n) * 80 + (b_k + ks * 16) * 2);
                MMA16816(acc[0][2 * jp],     a0, b[0], b[1]);
                MMA16816(acc[0][2 * jp + 1], a0, b[2], b[3]);
                MMA16816(acc[1][2 * jp],     a1, b[0], b[1]);
                MMA16816(acc[1][2 * jp + 1], a1, b[2], b[3]);
            }
        }
    };

    load_chunk(0, 0); CP_ASYNC_COMMIT();
    load_chunk(1, 1); CP_ASYNC_COMMIT();

    for (int c = 0; c < NUM_CHUNKS; c++) {
        CP_ASYNC_WAIT_1();
        __syncthreads();
        const int nc = c + 2;
        if (nc < NUM_CHUNKS) load_chunk(nc, nc % NSTAGE);
        CP_ASYNC_COMMIT();
        compute_stage(c % NSTAGE);
        __syncthreads();
    }

#pragma unroll
    for (int i = 0; i < 2; i++) {
        const int r0 = bm + wm * 32 + i * 16 + (lane >> 2);
#pragma unroll
        for (int j = 0; j < 8; j++) {
            const int col = bn + wn * 64 + j * 8 + (lane & 3) * 2;
            float2 v0; v0.x = acc[i][j][0]; v0.y = acc[i][j][1];
            float2 v1; v1.x = acc[i][j][2]; v1.y = acc[i][j][3];
            *(float2*)(g_Y + (size_t)r0 * N_DIM + col) = v0;
            *(float2*)(g_Y + (size_t)(r0 + 8) * N_DIM + col) = v1;
        }
    }
}

// ---------------------------------------------------------------------------
// Scan pass 1: membrane scan + fused bias + near-threshold chain flagging.
// ---------------------------------------------------------------------------
__global__ void __launch_bounds__(256)
scan_kernel(const float* __restrict__ bias, float* __restrict__ out)
{
    const int idx = blockIdx.x * blockDim.x + threadIdx.x;   // 0..32767
    const int b = idx >> 10;
    const int n = idx & 1023;

    const float* yp = g_Y + ((size_t)b * T_DIM) * N_DIM + n;
    float* op = out + (size_t)b * N_DIM + n;
    const float bv = bias[n];

    const float f = (float)exp(-0.01);
    const float omf = 1.0f - f;

    float v = 0.0f;
    bool flagged = false;

    for (int t = 0; t < T_DIM; t += 8) {
        float y[8];
#pragma unroll
        for (int j = 0; j < 8; j++)
            y[j] = yp[(size_t)(t + j) * N_DIM];
#pragma unroll
        for (int j = 0; j < 8; j++) {
            float yy = y[j] + bv;
            v = f * v + omf * yy;
            flagged |= (fabsf(v - 1.0f) < DELTA);
            float s = (v >= 1.0f) ? 1.0f : 0.0f;
            v = (s != 0.0f) ? 0.0f : v;
            op[(size_t)(t + j) * ((size_t)B_DIM * N_DIM)] = s;
        }
    }

    if (flagged) {
        int p = atomicAdd(&g_count, 1);
        g_list[p] = idx;
    }
}

// ---------------------------------------------------------------------------
// Correction: flagged chains get y recomputed with bitwise serial-k fp32 FMA
// (the order that matched the reference exactly in round 1).
// ---------------------------------------------------------------------------
__global__ void __launch_bounds__(256)
correct_kernel(const float* __restrict__ X, const float* __restrict__ W)
{
    const int cnt = g_count;
    const int total = cnt * T_DIM;
    for (int i = blockIdx.x * blockDim.x + threadIdx.x; i < total;
         i += gridDim.x * blockDim.x) {
        const int chain = g_list[i >> 9];
        const int t = i & 511;
        const int b = chain >> 10;
        const int n = chain & 1023;
        const float* xr = X + ((size_t)b * T_DIM + t) * K_DIM;
        const float* wr = W + (size_t)n * K_DIM;
        float acc = 0.0f;
#pragma unroll 8
        for (int k = 0; k < K_DIM; k++)
            acc = fmaf(xr[k], wr[k], acc);
        g_Y[((size_t)b * T_DIM + t) * N_DIM + n] = acc;
    }
}

// ---------------------------------------------------------------------------
// Scan pass 2: re-run the scan for flagged chains only (now exact y).
// ---------------------------------------------------------------------------
__global__ void __launch_bounds__(256)
scan2_kernel(const float* __restrict__ bias, float* __restrict__ out)
{
    const int j = blockIdx.x * blockDim.x + threadIdx.x;
    if (j >= g_count) return;
    const int chain = g_list[j];
    const int b = chain >> 10;
    const int n = chain & 1023;

    const float* yp = g_Y + ((size_t)b * T_DIM) * N_DIM + n;
    float* op = out + (size_t)b * N_DIM + n;
    const float bv = bias[n];

    const float f = (float)exp(-0.01);
    const float omf = 1.0f - f;

    float v = 0.0f;
    for (int t = 0; t < T_DIM; t++) {
        float yy = yp[(size_t)t * N_DIM] + bv;
        v = f * v + omf * yy;
        float s = (v >= 1.0f) ? 1.0f : 0.0f;
        v = (s != 0.0f) ? 0.0f : v;
        op[(size_t)t * ((size_t)B_DIM * N_DIM)] = s;
    }
}

// ---------------------------------------------------------------------------
extern "C" void kernel_launch(void* const* d_in, const int* in_sizes, int n_in,
                              void* d_out, int out_size)
{
    const float* x    = (const float*)d_in[0];   // [B, T, 1024]
    const float* W    = (const float*)d_in[1];   // [1024, 1024]
    const float* bias = (const float*)d_in[2];   // [1024]
    float* out        = (float*)d_out;           // [T, B, 1024]

    cudaFuncSetAttribute(gemm_kernel, cudaFuncAttributeMaxDynamicSharedMemorySize, SMEM_TOTAL);

    // 1) split fp32 -> 3x bf16 (X and W together); zero flag counter
    split_kernel<<<34816, 256>>>(x, W);

    // 2) HMMA GEMM into g_Y (6 segments accumulated in registers)
    dim3 grid(N_DIM / 128, M_DIM / 128);
    gemm_kernel<<<grid, 256, SMEM_TOTAL>>>();

    // 3) membrane scan + bias + flagging
    scan_kernel<<<(B_DIM * N_DIM) / 256, 256>>>(bias, out);

    // 4) exact serial-k recompute of y for flagged chains
    correct_kernel<<<1024, 256>>>(x, W);

    // 5) re-scan flagged chains with exact y
    scan2_kernel<<<(B_DIM * N_DIM) / 256, 256>>>(bias, out);
}

// round 5
// speedup vs baseline: 6.2003x; 6.2003x over previous
#include <cuda_runtime.h>
#include <cstdint>
#include <math.h>

// ---------------------------------------------------------------------------
// Problem dims
// ---------------------------------------------------------------------------
#define B_DIM 32
#define T_DIM 512
#define K_DIM 1024
#define N_DIM 1024
#define M_DIM (B_DIM * T_DIM)   // 16384

// ---------------------------------------------------------------------------
// Static device scratch (allocation-guard safe)
// ---------------------------------------------------------------------------
__device__ float g_Y[(size_t)M_DIM * N_DIM];   // 64 MB pre-activations

// ---------------------------------------------------------------------------
// SGEMM: Y[m][n] = sum_k X[m][k] * W[n][k]     (serial-k fp32, bitwise-exact
// vs reference; bias added in scan). 128x128 tile, BK=16, 256 threads,
// 8x8 per thread packed as 32 x fma.rn.f32x2 accumulators (Blackwell 2xFP32).
// Double-buffered smem, one __syncthreads per chunk.
// ---------------------------------------------------------------------------
#define BM 128
#define BN 128
#define BK 16
#define PAD 132    // row stride in floats (16B aligned, kills STS 4-way conflicts)

__global__ void __launch_bounds__(256, 2)
gemm_kernel(const float* __restrict__ A,      // [M_DIM, K_DIM]
            const float* __restrict__ W)      // [N_DIM, K_DIM]
{
    __shared__ float As[2][BK][PAD];
    __shared__ float Bs[2][BK][PAD];

    const int bm = blockIdx.y * BM;
    const int bn = blockIdx.x * BN;
    const int tid = threadIdx.x;

    // load mapping: 256 threads, each 2 float4 from A and 2 from W per chunk
    const int lr = tid >> 2;            // 0..63
    const int lc = (tid & 3) << 2;      // 0,4,8,12

    // compute mapping: 16x16 threads, 8x8 each
    const int ty = tid >> 4;            // 0..15
    const int tx = tid & 15;            // 0..15

    const float* Ab = A + (size_t)bm * K_DIM;
    const float* Wb = W + (size_t)bn * K_DIM;

    // 32 packed accumulators = 64 fp32. acc2[i][jp] = (acc[i][2jp], acc[i][2jp+1])
    unsigned long long acc2[8][4];
#pragma unroll
    for (int i = 0; i < 8; i++)
#pragma unroll
        for (int jp = 0; jp < 4; jp++) acc2[i][jp] = 0ULL;

    float4 a0, a1, w0, w1;

    auto ldg_chunk = [&](int k0) {
        a0 = *(const float4*)(Ab + (size_t)lr        * K_DIM + k0 + lc);
        a1 = *(const float4*)(Ab + (size_t)(lr + 64) * K_DIM + k0 + lc);
        w0 = *(const float4*)(Wb + (size_t)lr        * K_DIM + k0 + lc);
        w1 = *(const float4*)(Wb + (size_t)(lr + 64) * K_DIM + k0 + lc);
    };

    auto sts_chunk = [&](int buf) {
        As[buf][lc + 0][lr]      = a0.x; As[buf][lc + 1][lr]      = a0.y;
        As[buf][lc + 2][lr]      = a0.z; As[buf][lc + 3][lr]      = a0.w;
        As[buf][lc + 0][lr + 64] = a1.x; As[buf][lc + 1][lr + 64] = a1.y;
        As[buf][lc + 2][lr + 64] = a1.z; As[buf][lc + 3][lr + 64] = a1.w;
        Bs[buf][lc + 0][lr]      = w0.x; Bs[buf][lc + 1][lr]      = w0.y;
        Bs[buf][lc + 2][lr]      = w0.z; Bs[buf][lc + 3][lr]      = w0.w;
        Bs[buf][lc + 0][lr + 64] = w1.x; Bs[buf][lc + 1][lr + 64] = w1.y;
        Bs[buf][lc + 2][lr + 64] = w1.z; Bs[buf][lc + 3][lr + 64] = w1.w;
    };

    // prologue
    ldg_chunk(0);
    sts_chunk(0);
    __syncthreads();

    const int NCHUNK = K_DIM / BK;      // 64
    for (int c = 0; c < NCHUNK; c++) {
        const int buf = c & 1;
        if (c + 1 < NCHUNK) ldg_chunk((c + 1) * BK);

#pragma unroll
        for (int kk = 0; kk < BK; kk++) {
            float4 av0 = *(const float4*)&As[buf][kk][ty * 4];
            float4 av1 = *(const float4*)&As[buf][kk][64 + ty * 4];
            float4 bv0 = *(const float4*)&Bs[buf][kk][tx * 4];
            float4 bv1 = *(const float4*)&Bs[buf][kk][64 + tx * 4];

            // pack b pairs (two output columns per 64-bit reg)
            unsigned long long b2[4];
            asm("mov.b64 %0, {%1,%2};" : "=l"(b2[0]) : "f"(bv0.x), "f"(bv0.y));
            asm("mov.b64 %0, {%1,%2};" : "=l"(b2[1]) : "f"(bv0.z), "f"(bv0.w));
            asm("mov.b64 %0, {%1,%2};" : "=l"(b2[2]) : "f"(bv1.x), "f"(bv1.y));
            asm("mov.b64 %0, {%1,%2};" : "=l"(b2[3]) : "f"(bv1.z), "f"(bv1.w));

            // pack duplicated a values
            unsigned long long a2[8];
            asm("mov.b64 %0, {%1,%1};" : "=l"(a2[0]) : "f"(av0.x));
            asm("mov.b64 %0, {%1,%1};" : "=l"(a2[1]) : "f"(av0.y));
            asm("mov.b64 %0, {%1,%1};" : "=l"(a2[2]) : "f"(av0.z));
            asm("mov.b64 %0, {%1,%1};" : "=l"(a2[3]) : "f"(av0.w));
            asm("mov.b64 %0, {%1,%1};" : "=l"(a2[4]) : "f"(av1.x));
            asm("mov.b64 %0, {%1,%1};" : "=l"(a2[5]) : "f"(av1.y));
            asm("mov.b64 %0, {%1,%1};" : "=l"(a2[6]) : "f"(av1.z));
            asm("mov.b64 %0, {%1,%1};" : "=l"(a2[7]) : "f"(av1.w));

#pragma unroll
            for (int i = 0; i < 8; i++)
#pragma unroll
                for (int jp = 0; jp < 4; jp++)
                    asm("fma.rn.f32x2 %0, %1, %2, %0;"
                        : "+l"(acc2[i][jp]) : "l"(a2[i]), "l"(b2[jp]));
        }

        if (c + 1 < NCHUNK) sts_chunk(buf ^ 1);
        __syncthreads();
    }

    // epilogue: unpack and store
#pragma unroll
    for (int i = 0; i < 8; i++) {
        const int r = bm + ((i < 4) ? (ty * 4 + i) : (64 + ty * 4 + (i - 4)));
#pragma unroll
        for (int jb = 0; jb < 2; jb++) {
            float4 v;
            asm("mov.b64 {%0,%1}, %2;" : "=f"(v.x), "=f"(v.y) : "l"(acc2[i][jb * 2]));
            asm("mov.b64 {%0,%1}, %2;" : "=f"(v.z), "=f"(v.w) : "l"(acc2[i][jb * 2 + 1]));
            const int ccol = bn + jb * 64 + tx * 4;
            *(float4*)(g_Y + (size_t)r * N_DIM + ccol) = v;
        }
    }
}

// ---------------------------------------------------------------------------
// Membrane scan with fused bias. 1 float/thread (32768 threads), unroll 8.
// ---------------------------------------------------------------------------
__global__ void __launch_bounds__(256)
scan_kernel(const float* __restrict__ bias, float* __restrict__ out)
{
    const int idx = blockIdx.x * blockDim.x + threadIdx.x;   // 0..32767
    const int b = idx >> 10;
    const int n = idx & 1023;

    const float* yp = g_Y + ((size_t)b * T_DIM) * N_DIM + n;
    float* op = out + (size_t)b * N_DIM + n;
    const float bv = bias[n];

    const float f = (float)exp(-0.01);
    const float omf = 1.0f - f;

    float v = 0.0f;

    for (int t = 0; t < T_DIM; t += 8) {
        float y[8];
#pragma unroll
        for (int j = 0; j < 8; j++)
            y[j] = yp[(size_t)(t + j) * N_DIM];
#pragma unroll
        for (int j = 0; j < 8; j++) {
            float yy = y[j] + bv;
            v = f * v + omf * yy;
            float s = (v >= 1.0f) ? 1.0f : 0.0f;
            v = (s != 0.0f) ? 0.0f : v;
            op[(size_t)(t + j) * ((size_t)B_DIM * N_DIM)] = s;
        }
    }
}

// ---------------------------------------------------------------------------
extern "C" void kernel_launch(void* const* d_in, const int* in_sizes, int n_in,
                              void* d_out, int out_size)
{
    const float* x    = (const float*)d_in[0];   // [B, T, 1024]
    const float* W    = (const float*)d_in[1];   // [1024, 1024]
    const float* bias = (const float*)d_in[2];   // [1024]
    float* out        = (float*)d_out;           // [T, B, 1024]

    dim3 grid(N_DIM / BN, M_DIM / BM);           // (8, 128) = 1024 CTAs
    gemm_kernel<<<grid, 256>>>(x, W);

    scan_kernel<<<(B_DIM * N_DIM) / 256, 256>>>(bias, out);
}